// round 15
// baseline (speedup 1.0000x reference)
#include <cuda_runtime.h>
#include <cstdint>
#include <cstddef>

#define CHN 128
#define IMGH 48
#define IMGW 48
#define NPIX 2304              // 48*48
#define NHEAD 8
#define HDIM 16

typedef unsigned long long u64t;

// ---------------- f32x2 packed helpers (sm_103a) ----------------
__device__ __forceinline__ u64t pack2(float lo, float hi) {
    u64t d;
    asm("mov.b64 %0, {%1, %2};" : "=l"(d) : "r"(__float_as_uint(lo)), "r"(__float_as_uint(hi)));
    return d;
}
__device__ __forceinline__ u64t pack2s(float v) {
    u64t d;
    unsigned int u = __float_as_uint(v);
    asm("mov.b64 %0, {%1, %1};" : "=l"(d) : "r"(u));
    return d;
}
__device__ __forceinline__ void unpack2(u64t v, float& lo, float& hi) {
    unsigned int a, b;
    asm("mov.b64 {%0, %1}, %2;" : "=r"(a), "=r"(b) : "l"(v));
    lo = __uint_as_float(a); hi = __uint_as_float(b);
}
__device__ __forceinline__ u64t ffma2(u64t a, u64t b, u64t c) {
    u64t d;
    asm("fma.rn.f32x2 %0, %1, %2, %3;" : "=l"(d) : "l"(a), "l"(b), "l"(c));
    return d;
}
__device__ __forceinline__ u64t fmul2(u64t a, u64t b) {
    u64t d;
    asm("mul.rn.f32x2 %0, %1, %2;" : "=l"(d) : "l"(a), "l"(b));
    return d;
}
__device__ __forceinline__ u64t fadd2(u64t a, u64t b) {
    u64t d;
    asm("add.rn.f32x2 %0, %1, %2;" : "=l"(d) : "l"(a), "l"(b));
    return d;
}
// cp.async 16B (LDGSTS)
__device__ __forceinline__ void cp16(unsigned int dst_smem, const void* src) {
    asm volatile("cp.async.cg.shared.global [%0], [%1], 16;" :: "r"(dst_smem), "l"(src));
}
#define CP_COMMIT() asm volatile("cp.async.commit_group;" ::: "memory")
#define CP_WAIT(n)  asm volatile("cp.async.wait_group %0;" :: "n"(n) : "memory")

// ---------------- scratch (device globals; no allocation) ----------------
// q/k/v in head layout, interleaved pairs: [h][n][d][{mag,phase}] (32 floats/row)
__device__ float g_q[2 * CHN * NPIX];
__device__ float g_k[2 * CHN * NPIX];
__device__ float g_v[2 * CHN * NPIX];
__device__ float g_ar[CHN * NPIX];        // attention out real (c,n)
__device__ float g_ai[CHN * NPIX];        // attention out imag (c,n)

// invfreq[p] = 10000^(-2p/16) = 10^(-p/2)
__constant__ float c_invfreq[8] = {
    1.0f, 0.31622776601683794f, 0.1f, 0.031622776601683794f,
    0.01f, 0.0031622776601683794f, 0.001f, 0.00031622776601683794f
};

// ---------------- complex 3x3 conv (pad 1), f32x2 co-pair packing --------
// block (24, 8) = 192 threads; each thread: 2 contiguous pixels x 2 co (pair)
// grid (CHN/16 = 8 co-blocks, 48 rows, 3 tensors for qkv | 1 for o)
#define CO_T 16
#define CI_T 16

__global__ __launch_bounds__(192) void cconv_kernel(
    const float* __restrict__ xr_in, const float* __restrict__ xi_in,
    const float* __restrict__ wr0, const float* __restrict__ wi0,
    const float* __restrict__ br0, const float* __restrict__ bi0,
    const float* __restrict__ wr1, const float* __restrict__ wi1,
    const float* __restrict__ br1, const float* __restrict__ bi1,
    const float* __restrict__ wr2, const float* __restrict__ wi2,
    const float* __restrict__ br2, const float* __restrict__ bi2,
    float* __restrict__ yr_ext, float* __restrict__ yi_ext,
    int in_sel, int mode_base)
{
    __shared__ float xs_r[CI_T][3][IMGW + 4];   // rows 16B-aligned
    __shared__ float xs_i[CI_T][3][IMGW + 4];
    __shared__ float ws_r[CI_T][9][CO_T];       // co fastest -> co-pair LDS.64
    __shared__ float ws_i[CI_T][9][CO_T];

    const int mode = mode_base ? 3 : (int)blockIdx.z;
    const float* wr = (mode == 1) ? wr1 : (mode == 2) ? wr2 : wr0;
    const float* wi = (mode == 1) ? wi1 : (mode == 2) ? wi2 : wi0;
    const float* br = (mode == 1) ? br1 : (mode == 2) ? br2 : br0;
    const float* bi = (mode == 1) ? bi1 : (mode == 2) ? bi2 : bi0;

    const float* xr = in_sel ? g_ar : xr_in;
    const float* xi = in_sel ? g_ai : xi_in;

    const int tx = threadIdx.x;                // 0..23
    const int ty = threadIdx.y;                // 0..7
    const int y  = blockIdx.y;
    const int co0 = blockIdx.x * CO_T + ty * 2;
    const int tid = ty * 24 + tx;              // 0..191
    const int px0 = tx * 2;                    // first of pixel pair

    // packed accumulators over co pair: s_xy = sum of x-part * y-weight
    u64t s_rr0 = 0, s_ii0 = 0, s_ri0 = 0, s_ir0 = 0;   // pixel 0
    u64t s_rr1 = 0, s_ii1 = 0, s_ri1 = 0, s_ir1 = 0;   // pixel 1

    for (int ci0 = 0; ci0 < CHN; ci0 += CI_T) {
        __syncthreads();
        // x tile: CI_T x 3 rows x 50 used cols (zero-padded halo), both r & i
        for (int idx = tid; idx < CI_T * 3 * (IMGW + 2); idx += 192) {
            int ci  = idx / (3 * (IMGW + 2));
            int rem = idx % (3 * (IMGW + 2));
            int ry  = rem / (IMGW + 2);
            int rx  = rem % (IMGW + 2);
            int gy  = y + ry - 1;
            int gx  = rx - 1;
            float vr = 0.f, vi = 0.f;
            if ((unsigned)gy < (unsigned)IMGH && (unsigned)gx < (unsigned)IMGW) {
                int g = (ci0 + ci) * NPIX + gy * IMGW + gx;
                vr = xr[g]; vi = xi[g];
            }
            xs_r[ci][ry][rx] = vr;
            xs_i[ci][ry][rx] = vi;
        }
        // weights into [ci][k][co] layout (k fastest in gmem read -> coalesced)
        for (int idx = tid; idx < CO_T * CI_T * 9; idx += 192) {
            int k   = idx % 9;
            int col = (idx / 9) % CO_T;
            int ci  = idx / (9 * CO_T);
            int gw  = (blockIdx.x * CO_T + col) * (CHN * 9) + (ci0 + ci) * 9 + k;
            ws_r[ci][k][col] = wr[gw];
            ws_i[ci][k][col] = wi[gw];
        }
        __syncthreads();

        #pragma unroll 2
        for (int ci = 0; ci < CI_T; ci++) {
            // hoist my co-pair weights as packed u64 (aligned LDS.64)
            u64t wrp[9], wip[9];
            #pragma unroll
            for (int k = 0; k < 9; k++) {
                wrp[k] = *(const u64t*)&ws_r[ci][k][ty * 2];
                wip[k] = *(const u64t*)&ws_i[ci][k][ty * 2];
            }
            #pragma unroll
            for (int ky = 0; ky < 3; ky++) {
                float2 ra = *(const float2*)&xs_r[ci][ky][px0];
                float2 rb = *(const float2*)&xs_r[ci][ky][px0 + 2];
                float2 ia = *(const float2*)&xs_i[ci][ky][px0];
                float2 ib = *(const float2*)&xs_i[ci][ky][px0 + 2];
                float xr0t[3] = { ra.x, ra.y, rb.x };   // pixel0 taps
                float xr1t[3] = { ra.y, rb.x, rb.y };   // pixel1 taps
                float xi0t[3] = { ia.x, ia.y, ib.x };
                float xi1t[3] = { ia.y, ib.x, ib.y };
                #pragma unroll
                for (int kx = 0; kx < 3; kx++) {
                    const int k = ky * 3 + kx;
                    u64t xr0p = pack2s(xr0t[kx]);
                    u64t xi0p = pack2s(xi0t[kx]);
                    u64t xr1p = pack2s(xr1t[kx]);
                    u64t xi1p = pack2s(xi1t[kx]);
                    s_rr0 = ffma2(xr0p, wrp[k], s_rr0);
                    s_ii0 = ffma2(xi0p, wip[k], s_ii0);
                    s_ri0 = ffma2(xr0p, wip[k], s_ri0);
                    s_ir0 = ffma2(xi0p, wrp[k], s_ir0);
                    s_rr1 = ffma2(xr1p, wrp[k], s_rr1);
                    s_ii1 = ffma2(xi1p, wip[k], s_ii1);
                    s_ri1 = ffma2(xr1p, wip[k], s_ri1);
                    s_ir1 = ffma2(xi1p, wrp[k], s_ir1);
                }
            }
        }
    }

    // unpack and combine
    float rr0l, rr0h, ii0l, ii0h, ri0l, ri0h, ir0l, ir0h;
    float rr1l, rr1h, ii1l, ii1h, ri1l, ri1h, ir1l, ir1h;
    unpack2(s_rr0, rr0l, rr0h); unpack2(s_ii0, ii0l, ii0h);
    unpack2(s_ri0, ri0l, ri0h); unpack2(s_ir0, ir0l, ir0h);
    unpack2(s_rr1, rr1l, rr1h); unpack2(s_ii1, ii1l, ii1h);
    unpack2(s_ri1, ri1l, ri1h); unpack2(s_ir1, ir1l, ir1h);

    float ar00 = rr0l - ii0l, ar01 = rr0h - ii0h;
    float ai00 = ri0l + ir0l, ai01 = ri0h + ir0h;
    float ar10 = rr1l - ii1l, ar11 = rr1h - ii1h;
    float ai10 = ri1l + ir1l, ai11 = ri1h + ir1h;

    const float brv0 = br[co0], brv1 = br[co0 + 1];
    const float biv0 = bi[co0], biv1 = bi[co0 + 1];

    if (mode == 3) {
        int n0 = y * IMGW + px0;
        *(float2*)&yr_ext[co0 * NPIX + n0]       = make_float2(ar00 + brv0, ar10 + brv0);
        *(float2*)&yr_ext[(co0 + 1) * NPIX + n0] = make_float2(ar01 + brv1, ar11 + brv1);
        *(float2*)&yi_ext[co0 * NPIX + n0]       = make_float2(ai00 + biv0, ai10 + biv0);
        *(float2*)&yi_ext[(co0 + 1) * NPIX + n0] = make_float2(ai01 + biv1, ai11 + biv1);
        return;
    }

    // fused transform: (optional rotary) + magnitude/phase, interleaved pairs
    const int h    = co0 >> 4;
    const int pair = (co0 >> 1) & 7;
    float* gp = (mode == 0) ? g_q : (mode == 1) ? g_k : g_v;

    #pragma unroll
    for (int p = 0; p < 2; p++) {
        float r0 = (p ? ar10 : ar00) + brv0;
        float r1 = (p ? ar11 : ar01) + brv1;
        float i0 = (p ? ai10 : ai00) + biv0;
        float i1 = (p ? ai11 : ai01) + biv1;
        int n = y * IMGW + px0 + p;

        if (mode < 2) {
            float f = (float)n * c_invfreq[pair];
            float sn, cs;
            sincosf(f, &sn, &cs);
            float nr0 = r0 * cs - r1 * sn, nr1 = r1 * cs + r0 * sn;
            float ni0 = i0 * cs - i1 * sn, ni1 = i1 * cs + i0 * sn;
            r0 = nr0; r1 = nr1; i0 = ni0; i1 = ni1;
        }
        float m0 = sqrtf(r0 * r0 + i0 * i0), p0 = atan2f(i0, r0);
        float m1 = sqrtf(r1 * r1 + i1 * i1), p1 = atan2f(i1, r1);
        int base = (h * NPIX + n) * 32 + pair * 4;
        *(float4*)&gp[base] = make_float4(m0, p0, m1, p1);
    }
}

// ---------------- attention (f32x2, 2 rows/thread, cp.async 3-stage) -----
// block: 128 threads = 32 row-pairs x 4 key-splits; grid (36 q-tiles, 8 heads)
#define NQ 64
#define PAIRS 32
#define TK 32
#define KPT 8
#define NTILE (NPIX / TK)     // 72
#define TILE_F (2 * TK * 32)  // floats per KV tile buffer (2048)

__global__ __launch_bounds__(128, 2) void attn_kernel(
    float* __restrict__ qkm_o, float* __restrict__ qkp_o)
{
    __shared__ float kv3[3][TILE_F];                // 3 x 8KB KV buffers
    __shared__ u64t  red[2 * PAIRS * 2 * 17];       // reduction buffer (17.4KB)

    const int h  = blockIdx.y;
    const int q0 = blockIdx.x * NQ;
    const int t  = threadIdx.x;
    const int s  = t >> 5;          // key split 0..3 (one warp each)
    const int rr = t & 31;          // row-pair index
    const int r0 = rr * 2, r1 = r0 + 1;
    const int qi0 = q0 + r0, qi1 = q0 + r1;
    const float scale = 0.14433756729740643f;   // 1/sqrt(48)

    const unsigned int kvs_base = (unsigned int)__cvta_generic_to_shared(kv3);

    // q rows as packed (mag,phase) pairs, prescaled by `scale`
    u64t qa[16], qb[16];
    {
        u64t sc = pack2s(scale);
        const ulonglong2* p0 = (const ulonglong2*)(g_q + ((size_t)(h * NPIX + qi0)) * 32);
        const ulonglong2* p1 = (const ulonglong2*)(g_q + ((size_t)(h * NPIX + qi1)) * 32);
        #pragma unroll
        for (int d2 = 0; d2 < 8; d2++) {
            ulonglong2 v0 = p0[d2], v1 = p1[d2];
            qa[2 * d2]     = fmul2(v0.x, sc);
            qa[2 * d2 + 1] = fmul2(v0.y, sc);
            qb[2 * d2]     = fmul2(v1.x, sc);
            qb[2 * d2 + 1] = fmul2(v1.y, sc);
        }
    }

    float mmax0 = -1e30f, lsum0 = 0.f;
    float mmax1 = -1e30f, lsum1 = 0.f;
    u64t acc0[16], acc1[16];
    #pragma unroll
    for (int d = 0; d < 16; d++) { acc0[d] = 0ULL; acc1[d] = 0ULL; }

    // cp.async tile loader: thread t moves 4x16B (2 of K, 2 of V)
    const float* gK = g_k + ((size_t)h * NPIX) * 32;
    const float* gV = g_v + ((size_t)h * NPIX) * 32;
    auto issue_tile = [&](int tile, int buf) {
        unsigned int kb = kvs_base + (unsigned int)buf * (TILE_F * 4);
        size_t go = (size_t)tile * TK * 32;
        cp16(kb + t * 16,                 gK + go + (size_t)t * 4);
        cp16(kb + (t + 128) * 16,         gK + go + (size_t)(t + 128) * 4);
        cp16(kb + 4096 + t * 16,          gV + go + (size_t)t * 4);
        cp16(kb + 4096 + (t + 128) * 16,  gV + go + (size_t)(t + 128) * 4);
        CP_COMMIT();
    };

    // prologue: tiles 0,1 in flight
    issue_tile(0, 0);
    issue_tile(1, 1);

    int buf = 0;
    for (int it = 0; it < NTILE; it++) {
        if (it < NTILE - 1) { CP_WAIT(1); } else { CP_WAIT(0); }   // tile it landed
        __syncthreads();   // visible to all; buffer (it+2)%3 finished reading
        if (it + 2 < NTILE) {
            int nbuf = buf + 2; if (nbuf >= 3) nbuf -= 3;
            issue_tile(it + 2, nbuf);
        }

        const float* kvK = kv3[buf];
        const float* kvV = kv3[buf] + TK * 32;

        // scores for my 8 keys x 2 rows
        float sm0[KPT], sp0[KPT], sm1[KPT], sp1[KPT];
        float tmax0 = -1e30f, tmax1 = -1e30f;
        #pragma unroll
        for (int jj = 0; jj < KPT; jj++) {
            int j = s * KPT + jj;
            const ulonglong2* krow = (const ulonglong2*)(kvK + j * 32);
            u64t d0 = 0ULL, d1 = 0ULL;
            #pragma unroll
            for (int d2 = 0; d2 < 8; d2++) {
                ulonglong2 kk = krow[d2];
                d0 = ffma2(qa[2 * d2],     kk.x, d0);
                d0 = ffma2(qa[2 * d2 + 1], kk.y, d0);
                d1 = ffma2(qb[2 * d2],     kk.x, d1);
                d1 = ffma2(qb[2 * d2 + 1], kk.y, d1);
            }
            unpack2(d0, sm0[jj], sp0[jj]);
            unpack2(d1, sm1[jj], sp1[jj]);
            tmax0 = fmaxf(tmax0, fabsf(sm0[jj]));
            tmax1 = fmaxf(tmax1, fabsf(sm1[jj]));
        }

        // direct STG of score block (registers -> gmem)
        {
            size_t b0 = ((size_t)h * NPIX + qi0) * NPIX + it * TK + s * KPT;
            size_t b1 = ((size_t)h * NPIX + qi1) * NPIX + it * TK + s * KPT;
            *(float4*)(qkm_o + b0)     = make_float4(sm0[0], sm0[1], sm0[2], sm0[3]);
            *(float4*)(qkm_o + b0 + 4) = make_float4(sm0[4], sm0[5], sm0[6], sm0[7]);
            *(float4*)(qkp_o + b0)     = make_float4(sp0[0], sp0[1], sp0[2], sp0[3]);
            *(float4*)(qkp_o + b0 + 4) = make_float4(sp0[4], sp0[5], sp0[6], sp0[7]);
            *(float4*)(qkm_o + b1)     = make_float4(sm1[0], sm1[1], sm1[2], sm1[3]);
            *(float4*)(qkm_o + b1 + 4) = make_float4(sm1[4], sm1[5], sm1[6], sm1[7]);
            *(float4*)(qkp_o + b1)     = make_float4(sp1[0], sp1[1], sp1[2], sp1[3]);
            *(float4*)(qkp_o + b1 + 4) = make_float4(sp1[4], sp1[5], sp1[6], sp1[7]);
        }

        // tile-level online-softmax rescale (per row)
        float nm0 = fmaxf(mmax0, tmax0);
        float nm1 = fmaxf(mmax1, tmax1);
        float c0 = __expf(mmax0 - nm0);
        float c1 = __expf(mmax1 - nm1);
        lsum0 *= c0; lsum1 *= c1;
        u64t cp0 = pack2s(c0), cp1 = pack2s(c1);
        #pragma unroll
        for (int d = 0; d < 16; d++) {
            acc0[d] = fmul2(acc0[d], cp0);
            acc1[d] = fmul2(acc1[d], cp1);
        }
        mmax0 = nm0; mmax1 = nm1;

        #pragma unroll
        for (int jj = 0; jj < KPT; jj++) {
            int j = s * KPT + jj;
            float p0 = __expf(fabsf(sm0[jj]) - nm0);
            float p1 = __expf(fabsf(sm1[jj]) - nm1);
            lsum0 += p0; lsum1 += p1;
            u64t pp0 = pack2s(p0), pp1 = pack2s(p1);
            const ulonglong2* vrow = (const ulonglong2*)(kvV + j * 32);
            #pragma unroll
            for (int d2 = 0; d2 < 8; d2++) {
                ulonglong2 vv = vrow[d2];
                acc0[2 * d2]     = ffma2(pp0, vv.x, acc0[2 * d2]);
                acc0[2 * d2 + 1] = ffma2(pp0, vv.y, acc0[2 * d2 + 1]);
                acc1[2 * d2]     = ffma2(pp1, vv.x, acc1[2 * d2]);
                acc1[2 * d2 + 1] = ffma2(pp1, vv.y, acc1[2 * d2 + 1]);
            }
        }

        buf++; if (buf >= 3) buf = 0;
    }

    // ---- reduce 4 splits per row-pair (2 pairwise rounds via red) ----
    __syncthreads();
    // round A: splits 2,3 publish -> slots 0,1
    if (s >= 2) {
        u64t* dst = &red[(((s - 2) * PAIRS + rr) * 2) * 17];
        dst[0] = pack2(mmax0, lsum0);
        #pragma unroll
        for (int d = 0; d < 16; d++) dst[1 + d] = acc0[d];
        u64t* dst1 = dst + 17;
        dst1[0] = pack2(mmax1, lsum1);
        #pragma unroll
        for (int d = 0; d < 16; d++) dst1[1 + d] = acc1[d];
    }
    __syncthreads();
    if (s < 2) {
        const u64t* src = &red[((s * PAIRS + rr) * 2) * 17];
        float m2, l2;
        unpack2(src[0], m2, l2);
        float M  = fmaxf(mmax0, m2);
        float ca = __expf(mmax0 - M), cb = __expf(m2 - M);
        lsum0 = lsum0 * ca + l2 * cb;
        u64t cap = pack2s(ca), cbp = pack2s(cb);
        #pragma unroll
        for (int d = 0; d < 16; d++)
            acc0[d] = fadd2(fmul2(acc0[d], cap), fmul2(src[1 + d], cbp));
        mmax0 = M;

        const u64t* src1 = src + 17;
        unpack2(src1[0], m2, l2);
        M  = fmaxf(mmax1, m2);
        ca = __expf(mmax1 - M); cb = __expf(m2 - M);
        lsum1 = lsum1 * ca + l2 * cb;
        cap = pack2s(ca); cbp = pack2s(cb);
        #pragma unroll
        for (int d = 0; d < 16; d++)
            acc1[d] = fadd2(fmul2(acc1[d], cap), fmul2(src1[1 + d], cbp));
        mmax1 = M;
    }
    __syncthreads();
    // round B: split 1 publishes to slot 0
    if (s == 1) {
        u64t* dst = &red[(rr * 2) * 17];
        dst[0] = pack2(mmax0, lsum0);
        #pragma unroll
        for (int d = 0; d < 16; d++) dst[1 + d] = acc0[d];
        u64t* dst1 = dst + 17;
        dst1[0] = pack2(mmax1, lsum1);
        #pragma unroll
        for (int d = 0; d < 16; d++) dst1[1 + d] = acc1[d];
    }
    __syncthreads();
    if (s == 0) {
        #pragma unroll
        for (int row = 0; row < 2; row++) {
            const u64t* src = &red[(rr * 2 + row) * 17];
            float mm = row ? mmax1 : mmax0;
            float ll = row ? lsum1 : lsum0;
            u64t* ac = row ? acc1 : acc0;
            int   qi = row ? qi1 : qi0;
            float m2, l2;
            unpack2(src[0], m2, l2);
            float M  = fmaxf(mm, m2);
            float ca = __expf(mm - M), cb = __expf(m2 - M);
            float L  = ll * ca + l2 * cb;
            float invL = 1.f / L;
            u64t cap = pack2s(ca), cbp = pack2s(cb);
            #pragma unroll
            for (int d = 0; d < 16; d++) {
                u64t cmb = fadd2(fmul2(ac[d], cap), fmul2(src[1 + d], cbp));
                float amv, apv;
                unpack2(cmb, amv, apv);
                float omag = amv * invL;
                float oph  = apv * invL;
                float sn, cs;
                sincosf(oph, &sn, &cs);
                int c = h * HDIM + d;
                g_ar[c * NPIX + qi] = omag * cs;
                g_ai[c * NPIX + qi] = omag * sn;
            }
        }
    }
}

// ---------------- launch ----------------
extern "C" void kernel_launch(void* const* d_in, const int* in_sizes, int n_in,
                              void* d_out, int out_size)
{
    (void)in_sizes; (void)n_in; (void)out_size;
    const float* xr = (const float*)d_in[0];
    const float* xi = (const float*)d_in[1];
    float* out = (float*)d_out;

    const size_t O_OR  = 0;
    const size_t O_OI  = (size_t)CHN * NPIX;                  // 294912
    const size_t O_QKM = O_OI + (size_t)CHN * NPIX;           // 589824
    const size_t O_QKP = O_QKM + (size_t)NHEAD * NPIX * NPIX;

    dim3 cb(24, 8);

    // q, k, v complex convs batched in one launch (z = tensor)
    cconv_kernel<<<dim3(CHN / CO_T, IMGH, 3), cb>>>(
        xr, xi,
        (const float*)d_in[2],  (const float*)d_in[3],
        (const float*)d_in[4],  (const float*)d_in[5],
        (const float*)d_in[6],  (const float*)d_in[7],
        (const float*)d_in[8],  (const float*)d_in[9],
        (const float*)d_in[10], (const float*)d_in[11],
        (const float*)d_in[12], (const float*)d_in[13],
        nullptr, nullptr, 0, 0);

    // attention (writes qkm/qkp directly, a_r/a_i to scratch)
    attn_kernel<<<dim3(NPIX / NQ, NHEAD), 128>>>(out + O_QKM, out + O_QKP);

    // output complex conv: reads g_ar/g_ai, writes o_r/o_i
    cconv_kernel<<<dim3(CHN / CO_T, IMGH, 1), cb>>>(
        nullptr, nullptr,
        (const float*)d_in[14], (const float*)d_in[15],
        (const float*)d_in[16], (const float*)d_in[17],
        (const float*)d_in[14], (const float*)d_in[15],
        (const float*)d_in[16], (const float*)d_in[17],
        (const float*)d_in[14], (const float*)d_in[15],
        (const float*)d_in[16], (const float*)d_in[17],
        out + O_OR, out + O_OI, 1, 3);
}

// round 16
// speedup vs baseline: 1.1799x; 1.1799x over previous
#include <cuda_runtime.h>
#include <cstdint>
#include <cstddef>

#define CHN 128
#define IMGH 48
#define IMGW 48
#define NPIX 2304              // 48*48
#define NHEAD 8
#define HDIM 16

typedef unsigned long long u64t;

// ---------------- f32x2 packed helpers (sm_103a) ----------------
__device__ __forceinline__ u64t pack2(float lo, float hi) {
    u64t d;
    asm("mov.b64 %0, {%1, %2};" : "=l"(d) : "r"(__float_as_uint(lo)), "r"(__float_as_uint(hi)));
    return d;
}
__device__ __forceinline__ u64t pack2s(float v) {
    u64t d;
    unsigned int u = __float_as_uint(v);
    asm("mov.b64 %0, {%1, %1};" : "=l"(d) : "r"(u));
    return d;
}
__device__ __forceinline__ void unpack2(u64t v, float& lo, float& hi) {
    unsigned int a, b;
    asm("mov.b64 {%0, %1}, %2;" : "=r"(a), "=r"(b) : "l"(v));
    lo = __uint_as_float(a); hi = __uint_as_float(b);
}
__device__ __forceinline__ u64t ffma2(u64t a, u64t b, u64t c) {
    u64t d;
    asm("fma.rn.f32x2 %0, %1, %2, %3;" : "=l"(d) : "l"(a), "l"(b), "l"(c));
    return d;
}
__device__ __forceinline__ u64t fmul2(u64t a, u64t b) {
    u64t d;
    asm("mul.rn.f32x2 %0, %1, %2;" : "=l"(d) : "l"(a), "l"(b));
    return d;
}
__device__ __forceinline__ u64t fadd2(u64t a, u64t b) {
    u64t d;
    asm("add.rn.f32x2 %0, %1, %2;" : "=l"(d) : "l"(a), "l"(b));
    return d;
}

// ---------------- scratch (device globals; no allocation) ----------------
// q/k/v in head layout, interleaved pairs: [h][n][d][{mag,phase}] (32 floats/row)
__device__ float g_q[2 * CHN * NPIX];
__device__ float g_k[2 * CHN * NPIX];
__device__ float g_v[2 * CHN * NPIX];
__device__ float g_ar[CHN * NPIX];        // attention out real (c,n)
__device__ float g_ai[CHN * NPIX];        // attention out imag (c,n)

// invfreq[p] = 10000^(-2p/16) = 10^(-p/2)
__constant__ float c_invfreq[8] = {
    1.0f, 0.31622776601683794f, 0.1f, 0.031622776601683794f,
    0.01f, 0.0031622776601683794f, 0.001f, 0.00031622776601683794f
};

// ---------------- complex 3x3 conv (pad 1), f32x2 co-pair, 4 px/thread ---
// block (12, 8) = 96 threads; each thread: 4 contiguous pixels x 2 co (pair)
// grid (CHN/16 = 8 co-blocks, 48 rows, 3 tensors for qkv | 1 for o)
// mode (= blockIdx.z when mode_base==0, else 3)
#define CO_T 16
#define CI_T 16
#define XPOS (3 * 50)          // 150 x-tile positions per ci
#define WPOS (9 * CO_T)        // 144 weight positions per ci

__global__ __launch_bounds__(96) void cconv_kernel(
    const float* __restrict__ xr_in, const float* __restrict__ xi_in,
    const float* __restrict__ wr0, const float* __restrict__ wi0,
    const float* __restrict__ br0, const float* __restrict__ bi0,
    const float* __restrict__ wr1, const float* __restrict__ wi1,
    const float* __restrict__ br1, const float* __restrict__ bi1,
    const float* __restrict__ wr2, const float* __restrict__ wi2,
    const float* __restrict__ br2, const float* __restrict__ bi2,
    float* __restrict__ yr_ext, float* __restrict__ yi_ext,
    int in_sel, int mode_base)
{
    __shared__ float xs_r[CI_T][3][52];         // rows 16B-aligned (50 used)
    __shared__ float xs_i[CI_T][3][52];
    __shared__ float ws_r[CI_T][9][CO_T];       // co fastest -> co-pair LDS.64
    __shared__ float ws_i[CI_T][9][CO_T];

    const int mode = mode_base ? 3 : (int)blockIdx.z;
    const float* wr = (mode == 1) ? wr1 : (mode == 2) ? wr2 : wr0;
    const float* wi = (mode == 1) ? wi1 : (mode == 2) ? wi2 : wi0;
    const float* br = (mode == 1) ? br1 : (mode == 2) ? br2 : br0;
    const float* bi = (mode == 1) ? bi1 : (mode == 2) ? bi2 : bi0;

    const float* xr = in_sel ? g_ar : xr_in;
    const float* xi = in_sel ? g_ai : xi_in;

    const int tx = threadIdx.x;                // 0..11
    const int ty = threadIdx.y;                // 0..7
    const int y  = blockIdx.y;
    const int co0 = blockIdx.x * CO_T + ty * 2;
    const int tid = ty * 12 + tx;              // 0..95
    const int px0 = tx * 4;                    // first of 4-pixel group

    // ---- precompute staging indices (no div/mod/guards in chunk loop) ----
    // x tile: positions tid, tid+96 of 150; each = (ry, rx)
    int  s_ry[2], s_rx[2];
    bool s_ok[2];          // in-image (non-halo-zero) ?
    int  s_goff[2];        // gmem offset within channel (valid only if s_ok)
    #pragma unroll
    for (int u = 0; u < 2; u++) {
        int pos = tid + u * 96;
        bool act = pos < XPOS;
        int ry = act ? pos / 50 : 0;
        int rx = act ? pos % 50 : 0;
        int gy = y + ry - 1;
        int gx = rx - 1;
        s_ry[u] = ry; s_rx[u] = rx;
        s_ok[u] = act && (unsigned)gy < (unsigned)IMGH && (unsigned)gx < (unsigned)IMGW;
        s_goff[u] = gy * IMGW + gx;
        if (!act) s_ry[u] = -1;
    }
    // weights: positions tid, tid+96 of 144; each = (k, col)
    int  w_k[2], w_col[2];
    bool w_act[2];
    #pragma unroll
    for (int u = 0; u < 2; u++) {
        int pos = tid + u * 96;
        bool act = pos < WPOS;
        w_act[u] = act;
        w_k[u]   = act ? pos % 9 : 0;
        w_col[u] = act ? pos / 9 : 0;
    }

    // packed accumulators over co pair, per pixel p=0..3
    u64t s_rr[4] = {0,0,0,0}, s_ii[4] = {0,0,0,0};
    u64t s_ri[4] = {0,0,0,0}, s_ir[4] = {0,0,0,0};

    for (int ci0 = 0; ci0 < CHN; ci0 += CI_T) {
        __syncthreads();
        // x tile staging: fixed (ry,rx) per thread, loop over ci
        #pragma unroll
        for (int u = 0; u < 2; u++) {
            if (s_ry[u] >= 0) {
                float* dr = &xs_r[0][s_ry[u]][s_rx[u]];
                float* di = &xs_i[0][s_ry[u]][s_rx[u]];
                if (s_ok[u]) {
                    const float* pr = xr + (size_t)ci0 * NPIX + s_goff[u];
                    const float* pi = xi + (size_t)ci0 * NPIX + s_goff[u];
                    #pragma unroll 4
                    for (int ci = 0; ci < CI_T; ci++) {
                        dr[ci * (3 * 52)] = pr[ci * NPIX];
                        di[ci * (3 * 52)] = pi[ci * NPIX];
                    }
                } else {
                    #pragma unroll
                    for (int ci = 0; ci < CI_T; ci++) {
                        dr[ci * (3 * 52)] = 0.f;
                        di[ci * (3 * 52)] = 0.f;
                    }
                }
            }
        }
        // weight staging: fixed (k,col) per thread, loop over ci
        #pragma unroll
        for (int u = 0; u < 2; u++) {
            if (w_act[u]) {
                const int gbase = (blockIdx.x * CO_T + w_col[u]) * (CHN * 9) + ci0 * 9 + w_k[u];
                float* dr = &ws_r[0][w_k[u]][w_col[u]];
                float* di = &ws_i[0][w_k[u]][w_col[u]];
                #pragma unroll 4
                for (int ci = 0; ci < CI_T; ci++) {
                    dr[ci * (9 * CO_T)] = wr[gbase + ci * 9];
                    di[ci * (9 * CO_T)] = wi[gbase + ci * 9];
                }
            }
        }
        __syncthreads();

        #pragma unroll 2
        for (int ci = 0; ci < CI_T; ci++) {
            // hoist my co-pair weights as packed u64 (aligned LDS.64)
            u64t wrp[9], wip[9];
            #pragma unroll
            for (int k = 0; k < 9; k++) {
                wrp[k] = *(const u64t*)&ws_r[ci][k][ty * 2];
                wip[k] = *(const u64t*)&ws_i[ci][k][ty * 2];
            }
            #pragma unroll
            for (int ky = 0; ky < 3; ky++) {
                // 6 consecutive cols cover all 4 pixels' 3 taps
                float2 ra = *(const float2*)&xs_r[ci][ky][px0];
                float2 rb = *(const float2*)&xs_r[ci][ky][px0 + 2];
                float2 rc = *(const float2*)&xs_r[ci][ky][px0 + 4];
                float2 ia = *(const float2*)&xs_i[ci][ky][px0];
                float2 ib = *(const float2*)&xs_i[ci][ky][px0 + 2];
                float2 ic = *(const float2*)&xs_i[ci][ky][px0 + 4];
                u64t rp[6], ip[6];
                rp[0] = pack2s(ra.x); rp[1] = pack2s(ra.y);
                rp[2] = pack2s(rb.x); rp[3] = pack2s(rb.y);
                rp[4] = pack2s(rc.x); rp[5] = pack2s(rc.y);
                ip[0] = pack2s(ia.x); ip[1] = pack2s(ia.y);
                ip[2] = pack2s(ib.x); ip[3] = pack2s(ib.y);
                ip[4] = pack2s(ic.x); ip[5] = pack2s(ic.y);
                #pragma unroll
                for (int kx = 0; kx < 3; kx++) {
                    const int k = ky * 3 + kx;
                    #pragma unroll
                    for (int p = 0; p < 4; p++) {
                        u64t xrp = rp[p + kx];
                        u64t xip = ip[p + kx];
                        s_rr[p] = ffma2(xrp, wrp[k], s_rr[p]);
                        s_ii[p] = ffma2(xip, wip[k], s_ii[p]);
                        s_ri[p] = ffma2(xrp, wip[k], s_ri[p]);
                        s_ir[p] = ffma2(xip, wrp[k], s_ir[p]);
                    }
                }
            }
        }
    }

    const float brv0 = br[co0], brv1 = br[co0 + 1];
    const float biv0 = bi[co0], biv1 = bi[co0 + 1];

    // per-pixel combine
    float ar0[4], ar1[4], ai0[4], ai1[4];
    #pragma unroll
    for (int p = 0; p < 4; p++) {
        float rrl, rrh, iil, iih, ril, rih, irl, irh;
        unpack2(s_rr[p], rrl, rrh); unpack2(s_ii[p], iil, iih);
        unpack2(s_ri[p], ril, rih); unpack2(s_ir[p], irl, irh);
        ar0[p] = rrl - iil + brv0;   // co0
        ar1[p] = rrh - iih + brv1;   // co0+1
        ai0[p] = ril + irl + biv0;
        ai1[p] = rih + irh + biv1;
    }

    if (mode == 3) {
        int n0 = y * IMGW + px0;
        *(float4*)&yr_ext[co0 * NPIX + n0]       = make_float4(ar0[0], ar0[1], ar0[2], ar0[3]);
        *(float4*)&yr_ext[(co0 + 1) * NPIX + n0] = make_float4(ar1[0], ar1[1], ar1[2], ar1[3]);
        *(float4*)&yi_ext[co0 * NPIX + n0]       = make_float4(ai0[0], ai0[1], ai0[2], ai0[3]);
        *(float4*)&yi_ext[(co0 + 1) * NPIX + n0] = make_float4(ai1[0], ai1[1], ai1[2], ai1[3]);
        return;
    }

    // fused transform: (optional rotary) + magnitude/phase, interleaved pairs
    const int h    = co0 >> 4;
    const int pair = (co0 >> 1) & 7;
    float* gp = (mode == 0) ? g_q : (mode == 1) ? g_k : g_v;

    #pragma unroll
    for (int p = 0; p < 4; p++) {
        float r0 = ar0[p], r1 = ar1[p], i0 = ai0[p], i1 = ai1[p];
        int n = y * IMGW + px0 + p;

        if (mode < 2) {
            float f = (float)n * c_invfreq[pair];
            float sn, cs;
            sincosf(f, &sn, &cs);
            float nr0 = r0 * cs - r1 * sn, nr1 = r1 * cs + r0 * sn;
            float ni0 = i0 * cs - i1 * sn, ni1 = i1 * cs + i0 * sn;
            r0 = nr0; r1 = nr1; i0 = ni0; i1 = ni1;
        }
        float m0 = sqrtf(r0 * r0 + i0 * i0), p0 = atan2f(i0, r0);
        float m1 = sqrtf(r1 * r1 + i1 * i1), p1 = atan2f(i1, r1);
        int base = (h * NPIX + n) * 32 + pair * 4;
        *(float4*)&gp[base] = make_float4(m0, p0, m1, p1);
    }
}

// ---------------- attention (f32x2, 2 rows/thread, double-buffered KV) ---
// block: 128 threads = 32 row-pairs x 4 key-splits; grid (36 q-tiles, 8 heads)
#define NQ 64
#define PAIRS 32
#define TK 32
#define KPT 8
#define NTILE (NPIX / TK)     // 72

__global__ __launch_bounds__(128, 2) void attn_kernel(
    float* __restrict__ qkm_o, float* __restrict__ qkp_o)
{
    __shared__ float kv[2][2 * TK * 32];            // [buf][K tile | V tile], 16KB
    __shared__ u64t  red[2 * PAIRS * 2 * 17];       // reduction buffer (17.4KB)

    const int h  = blockIdx.y;
    const int q0 = blockIdx.x * NQ;
    const int t  = threadIdx.x;
    const int s  = t >> 5;          // key split 0..3 (one warp each)
    const int rr = t & 31;          // row-pair index
    const int r0 = rr * 2, r1 = r0 + 1;
    const int qi0 = q0 + r0, qi1 = q0 + r1;
    const float scale = 0.14433756729740643f;   // 1/sqrt(48)

    // q rows as packed (mag,phase) pairs, prescaled by `scale`
    u64t qa[16], qb[16];
    {
        u64t sc = pack2s(scale);
        const ulonglong2* p0 = (const ulonglong2*)(g_q + ((size_t)(h * NPIX + qi0)) * 32);
        const ulonglong2* p1 = (const ulonglong2*)(g_q + ((size_t)(h * NPIX + qi1)) * 32);
        #pragma unroll
        for (int d2 = 0; d2 < 8; d2++) {
            ulonglong2 v0 = p0[d2], v1 = p1[d2];
            qa[2 * d2]     = fmul2(v0.x, sc);
            qa[2 * d2 + 1] = fmul2(v0.y, sc);
            qb[2 * d2]     = fmul2(v1.x, sc);
            qb[2 * d2 + 1] = fmul2(v1.y, sc);
        }
    }

    float mmax0 = -1e30f, lsum0 = 0.f;
    float mmax1 = -1e30f, lsum1 = 0.f;
    u64t acc0[16], acc1[16];
    #pragma unroll
    for (int d = 0; d < 16; d++) { acc0[d] = 0ULL; acc1[d] = 0ULL; }

    // prologue: tile 0 -> kv[0]; tile 1 -> prefetch regs
    float4 pk0, pk1, pv0, pv1;
    {
        size_t gb = ((size_t)(h * NPIX)) * 32;
        pk0 = *(const float4*)(g_k + gb + (size_t)t * 4);
        pk1 = *(const float4*)(g_k + gb + (size_t)(t + 128) * 4);
        pv0 = *(const float4*)(g_v + gb + (size_t)t * 4);
        pv1 = *(const float4*)(g_v + gb + (size_t)(t + 128) * 4);
        ((float4*)kv[0])[t]                   = pk0;
        ((float4*)kv[0])[t + 128]             = pk1;
        ((float4*)(kv[0] + TK * 32))[t]       = pv0;
        ((float4*)(kv[0] + TK * 32))[t + 128] = pv1;
        gb += (size_t)TK * 32;
        pk0 = *(const float4*)(g_k + gb + (size_t)t * 4);
        pk1 = *(const float4*)(g_k + gb + (size_t)(t + 128) * 4);
        pv0 = *(const float4*)(g_v + gb + (size_t)t * 4);
        pv1 = *(const float4*)(g_v + gb + (size_t)(t + 128) * 4);
    }

    for (int it = 0; it < NTILE; it++) {
        __syncthreads();   // kv[it&1] visible; kv[(it+1)&1] free
        if (it + 1 < NTILE) {
            float* nb = kv[(it + 1) & 1];
            ((float4*)nb)[t]                   = pk0;
            ((float4*)nb)[t + 128]             = pk1;
            ((float4*)(nb + TK * 32))[t]       = pv0;
            ((float4*)(nb + TK * 32))[t + 128] = pv1;
        }
        if (it + 2 < NTILE) {
            size_t gb = ((size_t)(h * NPIX + (it + 2) * TK)) * 32;
            pk0 = *(const float4*)(g_k + gb + (size_t)t * 4);
            pk1 = *(const float4*)(g_k + gb + (size_t)(t + 128) * 4);
            pv0 = *(const float4*)(g_v + gb + (size_t)t * 4);
            pv1 = *(const float4*)(g_v + gb + (size_t)(t + 128) * 4);
        }

        const float* kvK = kv[it & 1];
        const float* kvV = kv[it & 1] + TK * 32;

        // scores for my 8 keys x 2 rows
        float sm0[KPT], sp0[KPT], sm1[KPT], sp1[KPT];
        float tmax0 = -1e30f, tmax1 = -1e30f;
        #pragma unroll
        for (int jj = 0; jj < KPT; jj++) {
            int j = s * KPT + jj;
            const ulonglong2* krow = (const ulonglong2*)(kvK + j * 32);
            u64t d0 = 0ULL, d1 = 0ULL;
            #pragma unroll
            for (int d2 = 0; d2 < 8; d2++) {
                ulonglong2 kk = krow[d2];
                d0 = ffma2(qa[2 * d2],     kk.x, d0);
                d0 = ffma2(qa[2 * d2 + 1], kk.y, d0);
                d1 = ffma2(qb[2 * d2],     kk.x, d1);
                d1 = ffma2(qb[2 * d2 + 1], kk.y, d1);
            }
            unpack2(d0, sm0[jj], sp0[jj]);
            unpack2(d1, sm1[jj], sp1[jj]);
            tmax0 = fmaxf(tmax0, fabsf(sm0[jj]));
            tmax1 = fmaxf(tmax1, fabsf(sm1[jj]));
        }

        // direct STG of score block (registers -> gmem)
        {
            size_t b0 = ((size_t)h * NPIX + qi0) * NPIX + it * TK + s * KPT;
            size_t b1 = ((size_t)h * NPIX + qi1) * NPIX + it * TK + s * KPT;
            *(float4*)(qkm_o + b0)     = make_float4(sm0[0], sm0[1], sm0[2], sm0[3]);
            *(float4*)(qkm_o + b0 + 4) = make_float4(sm0[4], sm0[5], sm0[6], sm0[7]);
            *(float4*)(qkp_o + b0)     = make_float4(sp0[0], sp0[1], sp0[2], sp0[3]);
            *(float4*)(qkp_o + b0 + 4) = make_float4(sp0[4], sp0[5], sp0[6], sp0[7]);
            *(float4*)(qkm_o + b1)     = make_float4(sm1[0], sm1[1], sm1[2], sm1[3]);
            *(float4*)(qkm_o + b1 + 4) = make_float4(sm1[4], sm1[5], sm1[6], sm1[7]);
            *(float4*)(qkp_o + b1)     = make_float4(sp1[0], sp1[1], sp1[2], sp1[3]);
            *(float4*)(qkp_o + b1 + 4) = make_float4(sp1[4], sp1[5], sp1[6], sp1[7]);
        }

        // tile-level online-softmax rescale (per row)
        float nm0 = fmaxf(mmax0, tmax0);
        float nm1 = fmaxf(mmax1, tmax1);
        float c0 = __expf(mmax0 - nm0);
        float c1 = __expf(mmax1 - nm1);
        lsum0 *= c0; lsum1 *= c1;
        u64t cp0 = pack2s(c0), cp1 = pack2s(c1);
        #pragma unroll
        for (int d = 0; d < 16; d++) {
            acc0[d] = fmul2(acc0[d], cp0);
            acc1[d] = fmul2(acc1[d], cp1);
        }
        mmax0 = nm0; mmax1 = nm1;

        #pragma unroll
        for (int jj = 0; jj < KPT; jj++) {
            int j = s * KPT + jj;
            float p0 = __expf(fabsf(sm0[jj]) - nm0);
            float p1 = __expf(fabsf(sm1[jj]) - nm1);
            lsum0 += p0; lsum1 += p1;
            u64t pp0 = pack2s(p0), pp1 = pack2s(p1);
            const ulonglong2* vrow = (const ulonglong2*)(kvV + j * 32);
            #pragma unroll
            for (int d2 = 0; d2 < 8; d2++) {
                ulonglong2 vv = vrow[d2];
                acc0[2 * d2]     = ffma2(pp0, vv.x, acc0[2 * d2]);
                acc0[2 * d2 + 1] = ffma2(pp0, vv.y, acc0[2 * d2 + 1]);
                acc1[2 * d2]     = ffma2(pp1, vv.x, acc1[2 * d2]);
                acc1[2 * d2 + 1] = ffma2(pp1, vv.y, acc1[2 * d2 + 1]);
            }
        }
    }

    // ---- reduce 4 splits per row-pair (2 pairwise rounds via red) ----
    __syncthreads();
    // round A: splits 2,3 publish -> slots 0,1
    if (s >= 2) {
        u64t* dst = &red[(((s - 2) * PAIRS + rr) * 2) * 17];
        dst[0] = pack2(mmax0, lsum0);
        #pragma unroll
        for (int d = 0; d < 16; d++) dst[1 + d] = acc0[d];
        u64t* dst1 = dst + 17;
        dst1[0] = pack2(mmax1, lsum1);
        #pragma unroll
        for (int d = 0; d < 16; d++) dst1[1 + d] = acc1[d];
    }
    __syncthreads();
    if (s < 2) {
        const u64t* src = &red[((s * PAIRS + rr) * 2) * 17];
        float m2, l2;
        unpack2(src[0], m2, l2);
        float M  = fmaxf(mmax0, m2);
        float ca = __expf(mmax0 - M), cb = __expf(m2 - M);
        lsum0 = lsum0 * ca + l2 * cb;
        u64t cap = pack2s(ca), cbp = pack2s(cb);
        #pragma unroll
        for (int d = 0; d < 16; d++)
            acc0[d] = fadd2(fmul2(acc0[d], cap), fmul2(src[1 + d], cbp));
        mmax0 = M;

        const u64t* src1 = src + 17;
        unpack2(src1[0], m2, l2);
        M  = fmaxf(mmax1, m2);
        ca = __expf(mmax1 - M); cb = __expf(m2 - M);
        lsum1 = lsum1 * ca + l2 * cb;
        cap = pack2s(ca); cbp = pack2s(cb);
        #pragma unroll
        for (int d = 0; d < 16; d++)
            acc1[d] = fadd2(fmul2(acc1[d], cap), fmul2(src1[1 + d], cbp));
        mmax1 = M;
    }
    __syncthreads();
    // round B: split 1 publishes to slot 0
    if (s == 1) {
        u64t* dst = &red[(rr * 2) * 17];
        dst[0] = pack2(mmax0, lsum0);
        #pragma unroll
        for (int d = 0; d < 16; d++) dst[1 + d] = acc0[d];
        u64t* dst1 = dst + 17;
        dst1[0] = pack2(mmax1, lsum1);
        #pragma unroll
        for (int d = 0; d < 16; d++) dst1[1 + d] = acc1[d];
    }
    __syncthreads();
    if (s == 0) {
        #pragma unroll
        for (int row = 0; row < 2; row++) {
            const u64t* src = &red[(rr * 2 + row) * 17];
            float mm = row ? mmax1 : mmax0;
            float ll = row ? lsum1 : lsum0;
            u64t* ac = row ? acc1 : acc0;
            int   qi = row ? qi1 : qi0;
            float m2, l2;
            unpack2(src[0], m2, l2);
            float M  = fmaxf(mm, m2);
            float ca = __expf(mm - M), cb = __expf(m2 - M);
            float L  = ll * ca + l2 * cb;
            float invL = 1.f / L;
            u64t cap = pack2s(ca), cbp = pack2s(cb);
            #pragma unroll
            for (int d = 0; d < 16; d++) {
                u64t cmb = fadd2(fmul2(ac[d], cap), fmul2(src[1 + d], cbp));
                float amv, apv;
                unpack2(cmb, amv, apv);
                float omag = amv * invL;
                float oph  = apv * invL;
                float sn, cs;
                sincosf(oph, &sn, &cs);
                int c = h * HDIM + d;
                g_ar[c * NPIX + qi] = omag * cs;
                g_ai[c * NPIX + qi] = omag * sn;
            }
        }
    }
}

// ---------------- launch ----------------
extern "C" void kernel_launch(void* const* d_in, const int* in_sizes, int n_in,
                              void* d_out, int out_size)
{
    (void)in_sizes; (void)n_in; (void)out_size;
    const float* xr = (const float*)d_in[0];
    const float* xi = (const float*)d_in[1];
    float* out = (float*)d_out;

    const size_t O_OR  = 0;
    const size_t O_OI  = (size_t)CHN * NPIX;                  // 294912
    const size_t O_QKM = O_OI + (size_t)CHN * NPIX;           // 589824
    const size_t O_QKP = O_QKM + (size_t)NHEAD * NPIX * NPIX;

    dim3 cb(12, 8);

    // q, k, v complex convs batched in one launch (z = tensor)
    cconv_kernel<<<dim3(CHN / CO_T, IMGH, 3), cb>>>(
        xr, xi,
        (const float*)d_in[2],  (const float*)d_in[3],
        (const float*)d_in[4],  (const float*)d_in[5],
        (const float*)d_in[6],  (const float*)d_in[7],
        (const float*)d_in[8],  (const float*)d_in[9],
        (const float*)d_in[10], (const float*)d_in[11],
        (const float*)d_in[12], (const float*)d_in[13],
        nullptr, nullptr, 0, 0);

    // attention (writes qkm/qkp directly, a_r/a_i to scratch)
    attn_kernel<<<dim3(NPIX / NQ, NHEAD), 128>>>(out + O_QKM, out + O_QKP);

    // output complex conv: reads g_ar/g_ai, writes o_r/o_i
    cconv_kernel<<<dim3(CHN / CO_T, IMGH, 1), cb>>>(
        nullptr, nullptr,
        (const float*)d_in[14], (const float*)d_in[15],
        (const float*)d_in[16], (const float*)d_in[17],
        (const float*)d_in[14], (const float*)d_in[15],
        (const float*)d_in[16], (const float*)d_in[17],
        (const float*)d_in[14], (const float*)d_in[15],
        (const float*)d_in[16], (const float*)d_in[17],
        out + O_OR, out + O_OI, 1, 3);
}